// round 1
// baseline (speedup 1.0000x reference)
#include <cuda_runtime.h>
#include <math.h>

// Problem constants
#define NBATCH   64
#define NCH      128
#define NPTS     256      // 16x16 image grid
#define MAPS     32       // BEV map size
#define NCELLS   (MAPS*MAPS)   // 1024
#define HMAXV    14
#define GROUPS   8        // channel groups per batch
#define CH_PER   (NCH / GROUPS)   // 16

__global__ __launch_bounds__(256)
void voxelize_kernel(const float* __restrict__ features,   // (64,128,256)
                     const float* __restrict__ depth,      // (64,1,256)
                     const float* __restrict__ cam,        // (3,256)
                     float* __restrict__ out)              // (64,128,32,32)
{
    __shared__ int besty[NCELLS];   // highest occupied y per cell, -1 = empty
    __shared__ int head [NCELLS];   // linked-list head of winning points
    __shared__ int nxt  [NPTS];

    const int tid = threadIdx.x;        // 0..255 == point id
    const int b   = blockIdx.y;         // batch
    const int g   = blockIdx.x;         // channel group

    // init shared
    #pragma unroll
    for (int i = 0; i < NCELLS / 256; i++) {
        besty[tid + i * 256] = -1;
        head [tid + i * 256] = -1;
    }

    // ---- per-point voxel index math (bit-exact vs JAX float32) ----
    const float d  = depth[b * NPTS + tid];
    const float cx = cam[          tid];
    const float cy = cam[  NPTS  + tid];
    const float cz = cam[2*NPTS  + tid];

    const float px = __fmul_rn(d, cx);
    const float py = __fadd_rn(__fmul_rn(d, cy), 1.72f);   // + CAM_HEIGHT
    const float pz = __fmul_rn(d, cz);

    const float CELLF = 0.1f;  // float32(3.2/32)
    const int xi = (int)floorf(__fdiv_rn(px, CELLF)) + (MAPS / 2);
    const int yi = (int)floorf(__fdiv_rn(py, CELLF));
    const int zi = (int)floorf(__fdiv_rn(pz, CELLF)) + MAPS;

    const bool valid = (xi >= 0) & (xi < MAPS) & (zi >= 0) & (zi < MAPS) & (yi < HMAXV);

    // replicate reference flat index semantics: flat = (z*32+x)*14 + y,
    // then decompose (y can in principle be negative; negative flat is dropped
    // exactly as segment_sum drops out-of-range indices).
    int cell = -1, ye = -1;
    if (valid) {
        const int vflat = (zi * MAPS + xi) * HMAXV + yi;
        if (vflat >= 0) {            // vflat < 1024*14 is guaranteed by bounds above
            cell = vflat / HMAXV;
            ye   = vflat - cell * HMAXV;
        }
    }
    __syncthreads();

    // ---- phase 1: per-cell highest occupied y ----
    if (cell >= 0) atomicMax(&besty[cell], ye);
    __syncthreads();

    // ---- phase 1.5: linked list of points at the winning voxel (sum duplicates) ----
    if (cell >= 0 && ye == besty[cell]) {
        nxt[tid] = atomicExch(&head[cell], tid);
    }
    __syncthreads();

    // ---- phase 2: stream dense output slab for this (batch, channel group) ----
    const float* fb = features + ((size_t)(b * NCH + g * CH_PER)) * NPTS;
    float*       ob = out      + ((size_t)(b * NCH + g * CH_PER)) * NCELLS;

    #pragma unroll 4
    for (int c = 0; c < CH_PER; c++) {
        const float* __restrict__ frow = fb + (size_t)c * NPTS;
        float*       __restrict__ orow = ob + (size_t)c * NCELLS;
        #pragma unroll
        for (int base = 0; base < NCELLS / 256; base++) {
            const int cl = base * 256 + tid;
            float s = 0.0f;
            int q = head[cl];
            while (q >= 0) {           // mostly 0 or 1 iterations
                s += frow[q];
                q = nxt[q];
            }
            orow[cl] = s;              // coalesced dense store (zeros for empty cells)
        }
    }
}

extern "C" void kernel_launch(void* const* d_in, const int* in_sizes, int n_in,
                              void* d_out, int out_size)
{
    const float* features = (const float*)d_in[0];   // 64*128*16*16
    const float* depth    = (const float*)d_in[1];   // 64*1*16*16
    const float* cam      = (const float*)d_in[2];   // 3*256
    float*       out      = (float*)d_out;           // 64*128*32*32

    dim3 grid(GROUPS, NBATCH);
    voxelize_kernel<<<grid, 256>>>(features, depth, cam, out);
}